// round 2
// baseline (speedup 1.0000x reference)
#include <cuda_runtime.h>
#include <cstdint>

// Problem shape (fixed by the dataset)
#define B_   4
#define H_   32
#define W_   32
#define C_   64
#define F_   128
#define NF   8               // one-hot features over magnitude m = 1..8
#define KC   (C_ * NF)       // 512 int8 per kernel position
#define KTOT (9 * KC)        // 4608
#define HP   34
#define WP   34
#define NPIX (B_ * H_ * W_)  // 4096
#define NOUT (NPIX * F_)     // 524288

// Scratch (device globals — no allocation)
__device__ __align__(16) int8_t g_Xf[B_ * HP * WP * KC];  // ~2.4 MB
__device__ __align__(16) int8_t g_Wt[F_ * KTOT];          // ~0.6 MB
__device__ __align__(16) int    g_Part[3][NOUT];          // 6 MB split-K partials

__device__ __forceinline__ int load_bits(const int* bp) {
    if (bp == nullptr) return 4;
    int b = bp[0];
    if (b < 1 || b > 30) b = (int)__int_as_float(b);
    if (b < 1 || b > 30) b = 4;
    return b;
}

// ---------------------------------------------------------------------------
// Feature expansion: g_Xf[(b,hp,wp), c, m-1] = floor(x * m / 2^bits) as s8.
// ---------------------------------------------------------------------------
__global__ void feat_kernel(const float* __restrict__ x, const int* __restrict__ bitsPtr) {
    int idx = blockIdx.x * blockDim.x + threadIdx.x;
    const int total = B_ * HP * WP * C_;
    if (idx >= total) return;
    int bits = load_bits(bitsPtr);

    int c  = idx & (C_ - 1);
    int r  = idx >> 6;
    int wp = r % WP; r /= WP;
    int hp = r % HP;
    int b  = r / HP;

    int xi = 0;
    if (hp >= 1 && hp <= H_ && wp >= 1 && wp <= W_)
        xi = (int)x[(((b * H_) + (hp - 1)) * W_ + (wp - 1)) * C_ + c];

    unsigned long long pack = 0ull;
#pragma unroll
    for (int m = 1; m <= 8; m++) {
        unsigned int v = (unsigned int)(unsigned char)(int8_t)((xi * m) >> bits);
        pack |= ((unsigned long long)v) << (8 * (m - 1));
    }
    reinterpret_cast<unsigned long long*>(g_Xf)[idx] = pack;
}

// ---------------------------------------------------------------------------
// Weight expansion: one-hot over m = |w| & mask, value = sign(w) as s8.
// Row-major [f][KTOT].
// ---------------------------------------------------------------------------
__global__ void wt_kernel(const float* __restrict__ kern, const int* __restrict__ bitsPtr) {
    int idx = blockIdx.x * blockDim.x + threadIdx.x;
    const int total = 9 * C_ * F_;
    if (idx >= total) return;
    int bits = load_bits(bitsPtr);
    int mask = (1 << bits) - 1;

    int f   = idx & (F_ - 1);
    int r   = idx >> 7;
    int c   = r & (C_ - 1);
    int pos = r >> 6;

    int wi = (int)kern[idx];
    int s  = (wi > 0) - (wi < 0);
    int m  = (wi < 0 ? -wi : wi) & mask;   // <= 8 for this dataset

    unsigned long long pack = 0ull;
    if (m >= 1 && m <= 8)
        pack = ((unsigned long long)(unsigned char)(int8_t)s) << (8 * (m - 1));

    reinterpret_cast<unsigned long long*>(g_Wt)[(f * KTOT + pos * KC + c * NF) >> 3] = pack;
}

// ---------------------------------------------------------------------------
// GEMM: Part[kg][4096,128] = sum over 3 kernel positions of A_pos * B_pos.
// int8 mma.sync m16n8k32, s32 accum (exact). Block 128x128, 8 warps (2x4),
// warp tile 64x32. Grid (32 M-tiles, 3 pos-groups). Plain stores, no atomics.
// ---------------------------------------------------------------------------
__device__ __forceinline__ void mma_s8(int c[4], const uint32_t a[4], const uint32_t b[2]) {
    asm volatile(
        "mma.sync.aligned.m16n8k32.row.col.s32.s8.s8.s32 "
        "{%0,%1,%2,%3}, {%4,%5,%6,%7}, {%8,%9}, {%0,%1,%2,%3};\n"
        : "+r"(c[0]), "+r"(c[1]), "+r"(c[2]), "+r"(c[3])
        : "r"(a[0]), "r"(a[1]), "r"(a[2]), "r"(a[3]), "r"(b[0]), "r"(b[1]));
}

__global__ __launch_bounds__(256, 2) void gemm_kernel() {
    // row stride 144 bytes: frag loads land on 32 distinct banks (4g+t4)
    __shared__ int8_t As[128][144];
    __shared__ int8_t Bs[128][144];

    const int tid = threadIdx.x;
    const int p0  = blockIdx.x * 128;

    const int tr = tid >> 3;      // 0..31 (row within pass)
    const int tc = tid & 7;       // 0..7  (16B chunk within 128B row)
    const int wa = tid >> 5, lane = tid & 31;
    const int wm = wa & 1, wn = wa >> 1;
    const int g = lane >> 2, t4 = lane & 3;

    // per-pass pixel decomposition (M rows)
    int bb4[4], hh4[4], ww4[4];
#pragma unroll
    for (int ps = 0; ps < 4; ps++) {
        int p = p0 + tr + ps * 32;
        bb4[ps] = p >> 10; hh4[ps] = (p >> 5) & 31; ww4[ps] = p & 31;
    }

    int acc[4][4][4];
#pragma unroll
    for (int mi = 0; mi < 4; mi++)
#pragma unroll
        for (int ni = 0; ni < 4; ni++)
#pragma unroll
            for (int e = 0; e < 4; e++) acc[mi][ni][e] = 0;

#pragma unroll 1
    for (int pp = 0; pp < 3; pp++) {
        const int pos = blockIdx.y * 3 + pp;
        const int di = pos / 3, dj = pos - di * 3;
        const int8_t* aRow[4];
        const int8_t* bRow[4];
#pragma unroll
        for (int ps = 0; ps < 4; ps++) {
            aRow[ps] = g_Xf + ((bb4[ps] * HP + hh4[ps] + di) * WP + (ww4[ps] + dj)) * KC + tc * 16;
            bRow[ps] = g_Wt + (tr + ps * 32) * KTOT + pos * KC + tc * 16;
        }

#pragma unroll 1
        for (int ks = 0; ks < 4; ks++) {
            const int k0 = ks * 128;
#pragma unroll
            for (int ps = 0; ps < 4; ps++) {
                *(uint4*)&As[tr + ps * 32][tc * 16] = *(const uint4*)(aRow[ps] + k0);
                *(uint4*)&Bs[tr + ps * 32][tc * 16] = *(const uint4*)(bRow[ps] + k0);
            }
            __syncthreads();

#pragma unroll
            for (int kk = 0; kk < 4; kk++) {
                const int kc = kk * 32 + t4 * 4;
                uint32_t a[4][4], b[4][2];
#pragma unroll
                for (int mi = 0; mi < 4; mi++) {
                    int r0 = wm * 64 + mi * 16 + g;
                    a[mi][0] = *(const uint32_t*)&As[r0][kc];
                    a[mi][1] = *(const uint32_t*)&As[r0 + 8][kc];
                    a[mi][2] = *(const uint32_t*)&As[r0][kc + 16];
                    a[mi][3] = *(const uint32_t*)&As[r0 + 8][kc + 16];
                }
#pragma unroll
                for (int ni = 0; ni < 4; ni++) {
                    int n = wn * 32 + ni * 8 + g;
                    b[ni][0] = *(const uint32_t*)&Bs[n][kc];
                    b[ni][1] = *(const uint32_t*)&Bs[n][kc + 16];
                }
#pragma unroll
                for (int mi = 0; mi < 4; mi++)
#pragma unroll
                    for (int ni = 0; ni < 4; ni++)
                        mma_s8(acc[mi][ni], a[mi], b[ni]);
            }
            __syncthreads();
        }
    }

    int* outp = g_Part[blockIdx.y];
#pragma unroll
    for (int mi = 0; mi < 4; mi++) {
        int r0 = p0 + wm * 64 + mi * 16 + g;
#pragma unroll
        for (int ni = 0; ni < 4; ni++) {
            int cc = wn * 32 + ni * 8 + t4 * 2;
            *(int2*)&outp[r0 * F_ + cc]       = make_int2(acc[mi][ni][0], acc[mi][ni][1]);
            *(int2*)&outp[(r0 + 8) * F_ + cc] = make_int2(acc[mi][ni][2], acc[mi][ni][3]);
        }
    }
}

// ---------------------------------------------------------------------------
// Reduce split-K partials + bias + relu, vectorized x4.
// ---------------------------------------------------------------------------
__global__ void reduce_kernel(float* __restrict__ out, const float* __restrict__ bias) {
    int i = blockIdx.x * blockDim.x + threadIdx.x;
    if (i >= NOUT / 4) return;
    int4 a = ((const int4*)g_Part[0])[i];
    int4 b = ((const int4*)g_Part[1])[i];
    int4 c = ((const int4*)g_Part[2])[i];
    float4 bv = __ldg(&((const float4*)bias)[i & 31]);   // F=128 -> 32 float4
    float4 o;
    o.x = fmaxf((float)(a.x + b.x + c.x) + bv.x, 0.0f);
    o.y = fmaxf((float)(a.y + b.y + c.y) + bv.y, 0.0f);
    o.z = fmaxf((float)(a.z + b.z + c.z) + bv.z, 0.0f);
    o.w = fmaxf((float)(a.w + b.w + c.w) + bv.w, 0.0f);
    ((float4*)out)[i] = o;
}

// ---------------------------------------------------------------------------
extern "C" void kernel_launch(void* const* d_in, const int* in_sizes, int n_in,
                              void* d_out, int out_size) {
    const float* x    = (const float*)d_in[0];
    const float* kern = (const float*)d_in[1];
    const float* bias = (const float*)d_in[2];
    const int*   bits = (n_in >= 4) ? (const int*)d_in[3] : nullptr;
    float* out = (float*)d_out;

    const int featTotal = B_ * HP * WP * C_;   // 295936
    const int wtTotal   = 9 * C_ * F_;         // 73728

    feat_kernel<<<(featTotal + 255) / 256, 256>>>(x, bits);
    wt_kernel<<<(wtTotal + 255) / 256, 256>>>(kern, bits);
    dim3 gg(NPIX / 128, 3);
    gemm_kernel<<<gg, 256>>>();
    reduce_kernel<<<(NOUT / 4 + 255) / 256, 256>>>(out, bias);
}

// round 3
// speedup vs baseline: 2.1753x; 2.1753x over previous
#include <cuda_runtime.h>
#include <cuda_bf16.h>
#include <cstdint>

#define B_   4
#define H_   32
#define W_   32
#define C_   64
#define F_   128
#define NF   8
#define KC   (C_ * NF)       // 512 bf16 per kernel position
#define KTOT (9 * KC)        // 4608
#define HP   34
#define WP   34
#define NPIX (B_ * H_ * W_)  // 4096
#define NOUT (NPIX * F_)     // 524288

#define LDA  72              // padded smem row stride (bf16 elems)

// Scratch (device globals — no allocation)
__device__ __align__(16) __nv_bfloat16 g_Xf[B_ * HP * WP * KC]; // ~4.7 MB
__device__ __align__(16) __nv_bfloat16 g_Wt[F_ * KTOT];         // ~1.2 MB

__device__ __forceinline__ int load_bits(const int* bp) {
    if (bp == nullptr) return 4;
    int b = bp[0];
    if (b < 1 || b > 30) b = (int)__int_as_float(b);
    if (b < 1 || b > 30) b = 4;
    return b;
}

// ---------------------------------------------------------------------------
// Feature expansion: g_Xf[(b,hp,wp), c, m-1] = floor(x*m / 2^bits), padded.
// ---------------------------------------------------------------------------
__global__ void feat_kernel(const float* __restrict__ x, const int* __restrict__ bitsPtr) {
    int idx = blockIdx.x * blockDim.x + threadIdx.x;
    const int total = B_ * HP * WP * C_;
    if (idx >= total) return;
    int bits = load_bits(bitsPtr);

    int c  = idx & (C_ - 1);
    int r  = idx >> 6;
    int wp = r % WP; r /= WP;
    int hp = r % HP;
    int b  = r / HP;

    int xi = 0;
    if (hp >= 1 && hp <= H_ && wp >= 1 && wp <= W_)
        xi = (int)x[(((b * H_) + (hp - 1)) * W_ + (wp - 1)) * C_ + c];

    __nv_bfloat16 hv[8];
#pragma unroll
    for (int m = 1; m <= 8; m++)
        hv[m - 1] = __float2bfloat16((float)((xi * m) >> bits));

    reinterpret_cast<uint4*>(g_Xf)[idx] = *reinterpret_cast<uint4*>(hv);
}

// ---------------------------------------------------------------------------
// Weight expansion: one-hot over m = |w| & mask, value sign(w). [f][KTOT].
// ---------------------------------------------------------------------------
__global__ void wt_kernel(const float* __restrict__ kern, const int* __restrict__ bitsPtr) {
    int idx = blockIdx.x * blockDim.x + threadIdx.x;
    const int total = 9 * C_ * F_;
    if (idx >= total) return;
    int bits = load_bits(bitsPtr);
    int mask = (1 << bits) - 1;

    int f   = idx & (F_ - 1);
    int r   = idx >> 7;
    int c   = r & (C_ - 1);
    int pos = r >> 6;

    int wi = (int)kern[idx];
    int s  = (wi > 0) - (wi < 0);
    int m  = (wi < 0 ? -wi : wi) & mask;

    __nv_bfloat16 hv[8];
#pragma unroll
    for (int mm = 1; mm <= 8; mm++)
        hv[mm - 1] = __float2bfloat16((float)((mm == m) ? s : 0));

    reinterpret_cast<uint4*>(g_Wt)[(f * KTOT + pos * KC + c * NF) >> 3] =
        *reinterpret_cast<uint4*>(hv);
}

// ---------------------------------------------------------------------------
__global__ void init_kernel(float4* __restrict__ out, const float4* __restrict__ bias) {
    int t = blockIdx.x * blockDim.x + threadIdx.x;
    if (t < NOUT / 4) out[t] = bias[t & 31];
}

__global__ void relu_kernel(float4* __restrict__ out) {
    int t = blockIdx.x * blockDim.x + threadIdx.x;
    if (t >= NOUT / 4) return;
    float4 v = out[t];
    v.x = fmaxf(v.x, 0.f); v.y = fmaxf(v.y, 0.f);
    v.z = fmaxf(v.z, 0.f); v.w = fmaxf(v.w, 0.f);
    out[t] = v;
}

// ---------------------------------------------------------------------------
// GEMM with ldmatrix + cp.async double buffering. Grid (32 M-tiles, 9 pos).
// Block 128x128, K=512 per position in 8 slabs of 64.
// ---------------------------------------------------------------------------
__device__ __forceinline__ void mma16816(float c[4], const uint32_t a[4], const uint32_t b[2]) {
    asm volatile(
        "mma.sync.aligned.m16n8k16.row.col.f32.bf16.bf16.f32 "
        "{%0,%1,%2,%3}, {%4,%5,%6,%7}, {%8,%9}, {%0,%1,%2,%3};\n"
        : "+f"(c[0]), "+f"(c[1]), "+f"(c[2]), "+f"(c[3])
        : "r"(a[0]), "r"(a[1]), "r"(a[2]), "r"(a[3]), "r"(b[0]), "r"(b[1]));
}

__device__ __forceinline__ void ldsm_x4(uint32_t r[4], uint32_t addr) {
    asm volatile("ldmatrix.sync.aligned.m8n8.x4.shared.b16 {%0,%1,%2,%3}, [%4];"
                 : "=r"(r[0]), "=r"(r[1]), "=r"(r[2]), "=r"(r[3]) : "r"(addr));
}
__device__ __forceinline__ void ldsm_x2(uint32_t r[2], uint32_t addr) {
    asm volatile("ldmatrix.sync.aligned.m8n8.x2.shared.b16 {%0,%1}, [%2];"
                 : "=r"(r[0]), "=r"(r[1]) : "r"(addr));
}
__device__ __forceinline__ void cp16(uint32_t smemAddr, const void* gmem) {
    asm volatile("cp.async.cg.shared.global [%0], [%1], 16;" :: "r"(smemAddr), "l"(gmem));
}

#define SLAB (128 * LDA)  // bf16 elems per (buffer, matrix)

__global__ __launch_bounds__(256, 2) void gemm_kernel(float* __restrict__ out) {
    extern __shared__ __nv_bfloat16 sm[];
    __nv_bfloat16* As = sm;              // [2][128][LDA]
    __nv_bfloat16* Bs = sm + 2 * SLAB;   // [2][128][LDA]

    const int tid  = threadIdx.x;
    const int pos  = blockIdx.y;
    const int di   = pos / 3, dj = pos - di * 3;
    const int p0   = blockIdx.x * 128;

    // ---- global source pointers (4 chunk rows per thread) ----
    const int cr = tid >> 3;          // 0..31
    const int cc = tid & 7;           // 16B chunk (8 bf16)
    const __nv_bfloat16* aSrc[4];
    const __nv_bfloat16* bSrc[4];
#pragma unroll
    for (int ps = 0; ps < 4; ps++) {
        int r = cr + ps * 32;
        int p = p0 + r;
        int bb = p >> 10, hh = (p >> 5) & 31, ww = p & 31;
        aSrc[ps] = g_Xf + ((bb * HP + hh + di) * WP + (ww + dj)) * KC + cc * 8;
        bSrc[ps] = g_Wt + r * KTOT + pos * KC + cc * 8;
    }
    uint32_t aDst[4], bDst[4];
#pragma unroll
    for (int ps = 0; ps < 4; ps++) {
        int r = cr + ps * 32;
        aDst[ps] = (uint32_t)__cvta_generic_to_shared(As + r * LDA + cc * 8);
        bDst[ps] = (uint32_t)__cvta_generic_to_shared(Bs + r * LDA + cc * 8);
    }

    // ---- fragment smem addresses (per warp) ----
    const int wa = tid >> 5, lane = tid & 31;
    const int wm = wa & 1, wn = wa >> 1;

    // A ldmatrix.x4: row = m0 + (lane&15), col = kc + 8*(lane>>4)
    const int aRow = wm * 64 + (lane & 15);
    const int aColX = (lane >> 4) << 3;
    // B ldmatrix.x2: row = n0 + (lane&7), col = kc + (lane&8)
    const int bRow = wn * 32 + (lane & 7);
    const int bColX = lane & 8;

    float acc[4][4][4];
#pragma unroll
    for (int mi = 0; mi < 4; mi++)
#pragma unroll
        for (int ni = 0; ni < 4; ni++)
#pragma unroll
            for (int e = 0; e < 4; e++) acc[mi][ni][e] = 0.0f;

    // ---- prefetch slab 0 ----
#pragma unroll
    for (int ps = 0; ps < 4; ps++) {
        cp16(aDst[ps], aSrc[ps]);
        cp16(bDst[ps], bSrc[ps]);
    }
    asm volatile("cp.async.commit_group;");

#pragma unroll 1
    for (int ks = 0; ks < 8; ks++) {
        const int cur = ks & 1;
        if (ks < 7) {
            const int nxt = (ks + 1) & 1;
            const int k0 = (ks + 1) * 64;
#pragma unroll
            for (int ps = 0; ps < 4; ps++) {
                cp16(aDst[ps] + nxt * SLAB * 2, aSrc[ps] + k0);
                cp16(bDst[ps] + nxt * SLAB * 2, bSrc[ps] + k0);
            }
            asm volatile("cp.async.commit_group;");
            asm volatile("cp.async.wait_group 1;");
        } else {
            asm volatile("cp.async.wait_group 0;");
        }
        __syncthreads();

        const __nv_bfloat16* Ab = As + cur * SLAB;
        const __nv_bfloat16* Bb = Bs + cur * SLAB;
#pragma unroll
        for (int kk = 0; kk < 4; kk++) {
            const int kc = kk * 16;
            uint32_t a[4][4], b[4][2];
#pragma unroll
            for (int mi = 0; mi < 4; mi++) {
                uint32_t ad = (uint32_t)__cvta_generic_to_shared(
                    Ab + (aRow + mi * 16) * LDA + kc + aColX);
                ldsm_x4(a[mi], ad);
            }
#pragma unroll
            for (int ni = 0; ni < 4; ni++) {
                uint32_t bd = (uint32_t)__cvta_generic_to_shared(
                    Bb + (bRow + ni * 8) * LDA + kc + bColX);
                ldsm_x2(b[ni], bd);
            }
#pragma unroll
            for (int mi = 0; mi < 4; mi++)
#pragma unroll
                for (int ni = 0; ni < 4; ni++)
                    mma16816(acc[mi][ni], a[mi], b[ni]);
        }
        __syncthreads();
    }

    // ---- split-K epilogue: exact-integer f32 atomics (order-independent) ----
    const int g = lane >> 2, t4 = lane & 3;
#pragma unroll
    for (int mi = 0; mi < 4; mi++) {
        int r0 = p0 + wm * 64 + mi * 16 + g;
#pragma unroll
        for (int ni = 0; ni < 4; ni++) {
            int ccol = wn * 32 + ni * 8 + t4 * 2;
            atomicAdd(&out[r0 * F_ + ccol],           acc[mi][ni][0]);
            atomicAdd(&out[r0 * F_ + ccol + 1],       acc[mi][ni][1]);
            atomicAdd(&out[(r0 + 8) * F_ + ccol],     acc[mi][ni][2]);
            atomicAdd(&out[(r0 + 8) * F_ + ccol + 1], acc[mi][ni][3]);
        }
    }
}

// ---------------------------------------------------------------------------
extern "C" void kernel_launch(void* const* d_in, const int* in_sizes, int n_in,
                              void* d_out, int out_size) {
    const float* x    = (const float*)d_in[0];
    const float* kern = (const float*)d_in[1];
    const float* bias = (const float*)d_in[2];
    const int*   bits = (n_in >= 4) ? (const int*)d_in[3] : nullptr;
    float* out = (float*)d_out;

    const int featTotal = B_ * HP * WP * C_;
    const int wtTotal   = 9 * C_ * F_;
    const int smemBytes = 4 * SLAB * 2;   // 2 bufs x (A+B) x 128 x LDA bf16

    static int smemSet = 0;
    if (!smemSet) {
        cudaFuncSetAttribute(gemm_kernel, cudaFuncAttributeMaxDynamicSharedMemorySize, smemBytes);
        smemSet = 1;
    }

    feat_kernel<<<(featTotal + 255) / 256, 256>>>(x, bits);
    wt_kernel<<<(wtTotal + 255) / 256, 256>>>(kern, bits);
    init_kernel<<<(NOUT / 4 + 255) / 256, 256>>>((float4*)out, (const float4*)bias);
    dim3 gg(NPIX / 128, 9);
    gemm_kernel<<<gg, 256, smemBytes>>>(out);
    relu_kernel<<<(NOUT / 4 + 255) / 256, 256>>>((float4*)out);
}

// round 4
// speedup vs baseline: 2.2703x; 1.0437x over previous
#include <cuda_runtime.h>
#include <cuda_bf16.h>
#include <cstdint>

#define B_   4
#define H_   32
#define W_   32
#define C_   64
#define F_   128
#define NF   8
#define KC   (C_ * NF)       // 512 bf16 per kernel position
#define KTOT (9 * KC)        // 4608
#define HP   34
#define WP   34
#define NPIX (B_ * H_ * W_)  // 4096
#define NOUT (NPIX * F_)     // 524288

#define LDA  72              // padded smem row stride (bf16 elems)

// Scratch (device globals — no allocation)
__device__ __align__(16) __nv_bfloat16 g_Xf[B_ * HP * WP * KC]; // ~4.7 MB
__device__ __align__(16) __nv_bfloat16 g_Wt[F_ * KTOT];         // ~1.2 MB

__device__ __forceinline__ int load_bits(const int* bp) {
    if (bp == nullptr) return 4;
    int b = bp[0];
    if (b < 1 || b > 30) b = (int)__int_as_float(b);
    if (b < 1 || b > 30) b = 4;
    return b;
}

#define FEAT_TOTAL (B_ * HP * WP * C_)   // 295936
#define WT_TOTAL   (9 * C_ * F_)         // 73728
#define INIT_TOTAL (NOUT / 4)            // 131072
#define PREP_TOTAL (FEAT_TOTAL + WT_TOTAL + INIT_TOTAL)

// ---------------------------------------------------------------------------
// Fused prep: feature expand + weight expand + out=bias init (range split).
// ---------------------------------------------------------------------------
__global__ void prep_kernel(const float* __restrict__ x, const float* __restrict__ kern,
                            const float4* __restrict__ bias4, float4* __restrict__ out4,
                            const int* __restrict__ bitsPtr) {
    int idx = blockIdx.x * blockDim.x + threadIdx.x;
    if (idx >= PREP_TOTAL) return;
    int bits = load_bits(bitsPtr);

    if (idx < FEAT_TOTAL) {
        // ---- feature expansion: g_Xf[(b,hp,wp), c, m-1] = (x*m) >> bits ----
        int c  = idx & (C_ - 1);
        int r  = idx >> 6;
        int wp = r % WP; r /= WP;
        int hp = r % HP;
        int b  = r / HP;

        int xi = 0;
        if (hp >= 1 && hp <= H_ && wp >= 1 && wp <= W_)
            xi = (int)x[(((b * H_) + (hp - 1)) * W_ + (wp - 1)) * C_ + c];

        __nv_bfloat16 hv[8];
#pragma unroll
        for (int m = 1; m <= 8; m++)
            hv[m - 1] = __float2bfloat16((float)((xi * m) >> bits));
        reinterpret_cast<uint4*>(g_Xf)[idx] = *reinterpret_cast<uint4*>(hv);
    } else if (idx < FEAT_TOTAL + WT_TOTAL) {
        // ---- weight expansion: one-hot over m = |w| & mask, value sign(w) ----
        int i = idx - FEAT_TOTAL;
        int mask = (1 << bits) - 1;
        int f   = i & (F_ - 1);
        int r   = i >> 7;
        int c   = r & (C_ - 1);
        int pos = r >> 6;

        int wi = (int)kern[i];
        int s  = (wi > 0) - (wi < 0);
        int m  = (wi < 0 ? -wi : wi) & mask;

        __nv_bfloat16 hv[8];
#pragma unroll
        for (int mm = 1; mm <= 8; mm++)
            hv[mm - 1] = __float2bfloat16((float)((mm == m) ? s : 0));
        reinterpret_cast<uint4*>(g_Wt)[(f * KTOT + pos * KC + c * NF) >> 3] =
            *reinterpret_cast<uint4*>(hv);
    } else {
        // ---- out = bias broadcast ----
        int t = idx - FEAT_TOTAL - WT_TOTAL;
        out4[t] = bias4[t & 31];
    }
}

__global__ void relu_kernel(float4* __restrict__ out) {
    int t = blockIdx.x * blockDim.x + threadIdx.x;
    if (t >= NOUT / 4) return;
    float4 v = out[t];
    v.x = fmaxf(v.x, 0.f); v.y = fmaxf(v.y, 0.f);
    v.z = fmaxf(v.z, 0.f); v.w = fmaxf(v.w, 0.f);
    out[t] = v;
}

// ---------------------------------------------------------------------------
// GEMM: block tile 64(M) x 128(N), warp tile 32x32 (8 warps, 2x4).
// Grid (64 M-tiles, 9 positions). ldmatrix + cp.async double buffering.
// ---------------------------------------------------------------------------
__device__ __forceinline__ void mma16816(float c[4], const uint32_t a[4], const uint32_t b[2]) {
    asm volatile(
        "mma.sync.aligned.m16n8k16.row.col.f32.bf16.bf16.f32 "
        "{%0,%1,%2,%3}, {%4,%5,%6,%7}, {%8,%9}, {%0,%1,%2,%3};\n"
        : "+f"(c[0]), "+f"(c[1]), "+f"(c[2]), "+f"(c[3])
        : "r"(a[0]), "r"(a[1]), "r"(a[2]), "r"(a[3]), "r"(b[0]), "r"(b[1]));
}
__device__ __forceinline__ void ldsm_x4(uint32_t r[4], uint32_t addr) {
    asm volatile("ldmatrix.sync.aligned.m8n8.x4.shared.b16 {%0,%1,%2,%3}, [%4];"
                 : "=r"(r[0]), "=r"(r[1]), "=r"(r[2]), "=r"(r[3]) : "r"(addr));
}
__device__ __forceinline__ void ldsm_x2(uint32_t r[2], uint32_t addr) {
    asm volatile("ldmatrix.sync.aligned.m8n8.x2.shared.b16 {%0,%1}, [%2];"
                 : "=r"(r[0]), "=r"(r[1]) : "r"(addr));
}
__device__ __forceinline__ void cp16(uint32_t smemAddr, const void* gmem) {
    asm volatile("cp.async.cg.shared.global [%0], [%1], 16;" :: "r"(smemAddr), "l"(gmem));
}

#define ASLAB (64 * LDA)    // bf16 elems per A buffer
#define BSLAB (128 * LDA)   // bf16 elems per B buffer

__global__ __launch_bounds__(256, 3) void gemm_kernel(float* __restrict__ out) {
    extern __shared__ __nv_bfloat16 sm[];
    __nv_bfloat16* As = sm;               // [2][64][LDA]
    __nv_bfloat16* Bs = sm + 2 * ASLAB;   // [2][128][LDA]

    const int tid = threadIdx.x;
    const int pos = blockIdx.y;
    const int di  = pos / 3, dj = pos - di * 3;
    const int p0  = blockIdx.x * 64;

    // ---- global sources ----
    const int cr = tid >> 3;          // 0..31
    const int cc = tid & 7;           // 16B chunk
    const __nv_bfloat16* aSrc[2];
    const __nv_bfloat16* bSrc[4];
    uint32_t aDst[2], bDst[4];
#pragma unroll
    for (int ps = 0; ps < 2; ps++) {
        int r = cr + ps * 32;
        int p = p0 + r;
        int bb = p >> 10, hh = (p >> 5) & 31, ww = p & 31;
        aSrc[ps] = g_Xf + ((bb * HP + hh + di) * WP + (ww + dj)) * KC + cc * 8;
        aDst[ps] = (uint32_t)__cvta_generic_to_shared(As + r * LDA + cc * 8);
    }
#pragma unroll
    for (int ps = 0; ps < 4; ps++) {
        int r = cr + ps * 32;
        bSrc[ps] = g_Wt + r * KTOT + pos * KC + cc * 8;
        bDst[ps] = (uint32_t)__cvta_generic_to_shared(Bs + r * LDA + cc * 8);
    }

    // ---- fragment addressing (per warp) ----
    const int wa = tid >> 5, lane = tid & 31;
    const int wm = wa & 1, wn = wa >> 1;
    const int aRow  = wm * 32 + (lane & 15);
    const int aColX = (lane >> 4) << 3;
    const int bRow  = wn * 32 + (lane & 7);
    const int bColX = lane & 8;

    float acc[2][4][4];
#pragma unroll
    for (int mi = 0; mi < 2; mi++)
#pragma unroll
        for (int ni = 0; ni < 4; ni++)
#pragma unroll
            for (int e = 0; e < 4; e++) acc[mi][ni][e] = 0.0f;

    // ---- prefetch slab 0 ----
#pragma unroll
    for (int ps = 0; ps < 2; ps++) cp16(aDst[ps], aSrc[ps]);
#pragma unroll
    for (int ps = 0; ps < 4; ps++) cp16(bDst[ps], bSrc[ps]);
    asm volatile("cp.async.commit_group;");

#pragma unroll 1
    for (int ks = 0; ks < 8; ks++) {
        const int cur = ks & 1;
        if (ks < 7) {
            const int nxt = (ks + 1) & 1;
            const int k0 = (ks + 1) * 64;
#pragma unroll
            for (int ps = 0; ps < 2; ps++) cp16(aDst[ps] + nxt * ASLAB * 2, aSrc[ps] + k0);
#pragma unroll
            for (int ps = 0; ps < 4; ps++) cp16(bDst[ps] + nxt * BSLAB * 2, bSrc[ps] + k0);
            asm volatile("cp.async.commit_group;");
            asm volatile("cp.async.wait_group 1;");
        } else {
            asm volatile("cp.async.wait_group 0;");
        }
        __syncthreads();

        const __nv_bfloat16* Ab = As + cur * ASLAB;
        const __nv_bfloat16* Bb = Bs + cur * BSLAB;
#pragma unroll
        for (int kk = 0; kk < 4; kk++) {
            const int kc = kk * 16;
            uint32_t a[2][4], b[4][2];
#pragma unroll
            for (int mi = 0; mi < 2; mi++) {
                uint32_t ad = (uint32_t)__cvta_generic_to_shared(
                    Ab + (aRow + mi * 16) * LDA + kc + aColX);
                ldsm_x4(a[mi], ad);
            }
#pragma unroll
            for (int ni = 0; ni < 4; ni++) {
                uint32_t bd = (uint32_t)__cvta_generic_to_shared(
                    Bb + (bRow + ni * 8) * LDA + kc + bColX);
                ldsm_x2(b[ni], bd);
            }
#pragma unroll
            for (int mi = 0; mi < 2; mi++)
#pragma unroll
                for (int ni = 0; ni < 4; ni++)
                    mma16816(acc[mi][ni], a[mi], b[ni]);
        }
        __syncthreads();
    }

    // ---- split-K epilogue: exact-integer f32 atomics ----
    const int g = lane >> 2, t4 = lane & 3;
#pragma unroll
    for (int mi = 0; mi < 2; mi++) {
        int r0 = p0 + wm * 32 + mi * 16 + g;
#pragma unroll
        for (int ni = 0; ni < 4; ni++) {
            int ccol = wn * 32 + ni * 8 + t4 * 2;
            atomicAdd(&out[r0 * F_ + ccol],           acc[mi][ni][0]);
            atomicAdd(&out[r0 * F_ + ccol + 1],       acc[mi][ni][1]);
            atomicAdd(&out[(r0 + 8) * F_ + ccol],     acc[mi][ni][2]);
            atomicAdd(&out[(r0 + 8) * F_ + ccol + 1], acc[mi][ni][3]);
        }
    }
}

// ---------------------------------------------------------------------------
extern "C" void kernel_launch(void* const* d_in, const int* in_sizes, int n_in,
                              void* d_out, int out_size) {
    const float* x    = (const float*)d_in[0];
    const float* kern = (const float*)d_in[1];
    const float* bias = (const float*)d_in[2];
    const int*   bits = (n_in >= 4) ? (const int*)d_in[3] : nullptr;
    float* out = (float*)d_out;

    const int smemBytes = (2 * ASLAB + 2 * BSLAB) * 2;   // 55296 bytes

    static int smemSet = 0;
    if (!smemSet) {
        cudaFuncSetAttribute(gemm_kernel, cudaFuncAttributeMaxDynamicSharedMemorySize, smemBytes);
        smemSet = 1;
    }

    prep_kernel<<<(PREP_TOTAL + 255) / 256, 256>>>(x, kern, (const float4*)bias,
                                                   (float4*)out, bits);
    dim3 gg(NPIX / 64, 9);
    gemm_kernel<<<gg, 256, smemBytes>>>(out);
    relu_kernel<<<(NOUT / 4 + 255) / 256, 256>>>((float4*)out);
}

// round 5
// speedup vs baseline: 2.3516x; 1.0358x over previous
#include <cuda_runtime.h>
#include <cuda_fp8.h>
#include <cstdint>

#define B_   4
#define H_   32
#define W_   32
#define C_   64
#define F_   128
#define NF   8
#define KC   (C_ * NF)       // 512 fp8 per kernel position
#define KTOT (9 * KC)        // 4608
#define HP   34
#define WP   34
#define NPIX (B_ * H_ * W_)  // 4096
#define NOUT (NPIX * F_)     // 524288

#define LDB  144             // smem row stride in BYTES (conflict-free ldmatrix)

// Scratch (device globals — no allocation)
__device__ __align__(16) uint8_t g_Xf[B_ * HP * WP * KC]; // ~2.4 MB e4m3
__device__ __align__(16) uint8_t g_Wt[F_ * KTOT];         // ~0.6 MB e4m3

__device__ __forceinline__ int load_bits(const int* bp) {
    if (bp == nullptr) return 4;
    int b = bp[0];
    if (b < 1 || b > 30) b = (int)__int_as_float(b);
    if (b < 1 || b > 30) b = 4;
    return b;
}

__device__ __forceinline__ uint8_t to_e4m3(float f) {
    return (uint8_t)__nv_cvt_float_to_fp8(f, __NV_SATFINITE, __NV_E4M3);
}

#define FEAT_TOTAL (B_ * HP * WP * C_)   // 295936
#define WT_TOTAL   (9 * C_ * F_)         // 73728
#define INIT_TOTAL (NOUT / 4)            // 131072
#define PREP_TOTAL (FEAT_TOTAL + WT_TOTAL + INIT_TOTAL)

// ---------------------------------------------------------------------------
// Fused prep: feature expand (e4m3) + weight expand (e4m3) + out=bias init.
// ---------------------------------------------------------------------------
__global__ void prep_kernel(const float* __restrict__ x, const float* __restrict__ kern,
                            const float4* __restrict__ bias4, float4* __restrict__ out4,
                            const int* __restrict__ bitsPtr) {
    int idx = blockIdx.x * blockDim.x + threadIdx.x;
    if (idx >= PREP_TOTAL) return;
    int bits = load_bits(bitsPtr);

    if (idx < FEAT_TOTAL) {
        int c  = idx & (C_ - 1);
        int r  = idx >> 6;
        int wp = r % WP; r /= WP;
        int hp = r % HP;
        int b  = r / HP;

        int xi = 0;
        if (hp >= 1 && hp <= H_ && wp >= 1 && wp <= W_)
            xi = (int)x[(((b * H_) + (hp - 1)) * W_ + (wp - 1)) * C_ + c];

        uint64_t pack = 0;
#pragma unroll
        for (int m = 1; m <= 8; m++)
            pack |= (uint64_t)to_e4m3((float)((xi * m) >> bits)) << (8 * (m - 1));
        reinterpret_cast<uint64_t*>(g_Xf)[idx] = pack;
    } else if (idx < FEAT_TOTAL + WT_TOTAL) {
        int i = idx - FEAT_TOTAL;
        int mask = (1 << bits) - 1;
        int f   = i & (F_ - 1);
        int r   = i >> 7;
        int c   = r & (C_ - 1);
        int pos = r >> 6;

        int wi = (int)kern[i];
        int s  = (wi > 0) - (wi < 0);
        int m  = (wi < 0 ? -wi : wi) & mask;

        uint64_t pack = 0;
        if (m >= 1 && m <= 8)
            pack = (uint64_t)(s > 0 ? 0x38u : 0xB8u) << (8 * (m - 1)); // ±1 in e4m3
        reinterpret_cast<uint64_t*>(g_Wt)[f * (KTOT / 8) + pos * (KC / 8) + c] = pack;
    } else {
        int t = idx - FEAT_TOTAL - WT_TOTAL;
        out4[t] = bias4[t & 31];
    }
}

__global__ void relu_kernel(float4* __restrict__ out) {
    int t = blockIdx.x * blockDim.x + threadIdx.x;
    if (t >= NOUT / 4) return;
    float4 v = out[t];
    v.x = fmaxf(v.x, 0.f); v.y = fmaxf(v.y, 0.f);
    v.z = fmaxf(v.z, 0.f); v.w = fmaxf(v.w, 0.f);
    out[t] = v;
}

// ---------------------------------------------------------------------------
// FP8 GEMM: block 64(M) x 128(N), 8 warps 2x4 (warp 32x32), grid (64, 9).
// mma m16n8k32 e4m3 -> f32 (exact). cp.async double-buffered, 4 slabs of 128B.
// ---------------------------------------------------------------------------
__device__ __forceinline__ void mma_e4m3(float c[4], const uint32_t a[4], const uint32_t b0,
                                         const uint32_t b1) {
    asm volatile(
        "mma.sync.aligned.m16n8k32.row.col.f32.e4m3.e4m3.f32 "
        "{%0,%1,%2,%3}, {%4,%5,%6,%7}, {%8,%9}, {%0,%1,%2,%3};\n"
        : "+f"(c[0]), "+f"(c[1]), "+f"(c[2]), "+f"(c[3])
        : "r"(a[0]), "r"(a[1]), "r"(a[2]), "r"(a[3]), "r"(b0), "r"(b1));
}
__device__ __forceinline__ void ldsm_x4(uint32_t r[4], uint32_t addr) {
    asm volatile("ldmatrix.sync.aligned.m8n8.x4.shared.b16 {%0,%1,%2,%3}, [%4];"
                 : "=r"(r[0]), "=r"(r[1]), "=r"(r[2]), "=r"(r[3]) : "r"(addr));
}
__device__ __forceinline__ void cp16(uint32_t smemAddr, const void* gmem) {
    asm volatile("cp.async.cg.shared.global [%0], [%1], 16;" :: "r"(smemAddr), "l"(gmem));
}

#define ASLAB (64 * LDB)     // bytes per A buffer (64 rows)
#define BSLAB (128 * LDB)    // bytes per B buffer (128 rows)
#define SMEMB (2 * ASLAB + 2 * BSLAB)   // 55296 bytes

__global__ __launch_bounds__(256, 3) void gemm_kernel(float* __restrict__ out) {
    extern __shared__ uint8_t sm[];
    uint8_t* As = sm;               // [2][64][LDB]
    uint8_t* Bs = sm + 2 * ASLAB;   // [2][128][LDB]

    const int tid = threadIdx.x;
    const int pos = blockIdx.y;
    const int di  = pos / 3, dj = pos - di * 3;
    const int p0  = blockIdx.x * 64;

    // ---- global sources: 16B chunks, slab = 128 bytes of K ----
    const int cr = tid >> 3;          // 0..31
    const int cc = tid & 7;           // chunk within 128B row
    const uint8_t* aSrc[2];
    const uint8_t* bSrc[4];
    uint32_t aDst[2], bDst[4];
#pragma unroll
    for (int ps = 0; ps < 2; ps++) {
        int r = cr + ps * 32;
        int p = p0 + r;
        int bb = p >> 10, hh = (p >> 5) & 31, ww = p & 31;
        aSrc[ps] = g_Xf + ((bb * HP + hh + di) * WP + (ww + dj)) * KC + cc * 16;
        aDst[ps] = (uint32_t)__cvta_generic_to_shared(As + r * LDB + cc * 16);
    }
#pragma unroll
    for (int ps = 0; ps < 4; ps++) {
        int r = cr + ps * 32;
        bSrc[ps] = g_Wt + r * KTOT + pos * KC + cc * 16;
        bDst[ps] = (uint32_t)__cvta_generic_to_shared(Bs + r * LDB + cc * 16);
    }

    // ---- fragment addressing ----
    const int wa = tid >> 5, lane = tid & 31;
    const int wm = wa & 1, wn = wa >> 1;
    const int fRow  = lane & 15;            // row within 16-row ldsm group
    const int fColB = (lane >> 4) << 4;     // 0 or 16 bytes

    float acc[2][4][4];
#pragma unroll
    for (int mi = 0; mi < 2; mi++)
#pragma unroll
        for (int j = 0; j < 4; j++)
#pragma unroll
            for (int e = 0; e < 4; e++) acc[mi][j][e] = 0.0f;

    // ---- prefetch slab 0 ----
#pragma unroll
    for (int ps = 0; ps < 2; ps++) cp16(aDst[ps], aSrc[ps]);
#pragma unroll
    for (int ps = 0; ps < 4; ps++) cp16(bDst[ps], bSrc[ps]);
    asm volatile("cp.async.commit_group;");

#pragma unroll 1
    for (int ks = 0; ks < 4; ks++) {
        const int cur = ks & 1;
        if (ks < 3) {
            const int nxt = (ks + 1) & 1;
            const int k0 = (ks + 1) * 128;
#pragma unroll
            for (int ps = 0; ps < 2; ps++) cp16(aDst[ps] + nxt * ASLAB, aSrc[ps] + k0);
#pragma unroll
            for (int ps = 0; ps < 4; ps++) cp16(bDst[ps] + nxt * BSLAB, bSrc[ps] + k0);
            asm volatile("cp.async.commit_group;");
            asm volatile("cp.async.wait_group 1;");
        } else {
            asm volatile("cp.async.wait_group 0;");
        }
        __syncthreads();

        const uint8_t* Ab = As + cur * ASLAB;
        const uint8_t* Bb = Bs + cur * BSLAB;
#pragma unroll
        for (int kk = 0; kk < 4; kk++) {           // 4 x k32 per 128B slab
            const int kcB = kk * 32;
            uint32_t a[2][4], b[2][4];
#pragma unroll
            for (int mi = 0; mi < 2; mi++) {
                uint32_t ad = (uint32_t)__cvta_generic_to_shared(
                    Ab + (wm * 32 + mi * 16 + fRow) * LDB + kcB + fColB);
                ldsm_x4(a[mi], ad);
            }
#pragma unroll
            for (int ni = 0; ni < 2; ni++) {
                uint32_t bd = (uint32_t)__cvta_generic_to_shared(
                    Bb + (wn * 32 + ni * 16 + fRow) * LDB + kcB + fColB);
                ldsm_x4(b[ni], bd);
            }
            // n8-group j: frags {b[j>>1][j&1], b[j>>1][(j&1)+2]}
#pragma unroll
            for (int mi = 0; mi < 2; mi++)
#pragma unroll
                for (int j = 0; j < 4; j++)
                    mma_e4m3(acc[mi][j], a[mi], b[j >> 1][j & 1], b[j >> 1][(j & 1) + 2]);
        }
        __syncthreads();
    }

    // ---- split-K epilogue: exact-integer f32 atomics ----
    const int g = lane >> 2, t4 = lane & 3;
#pragma unroll
    for (int mi = 0; mi < 2; mi++) {
        int r0 = p0 + wm * 32 + mi * 16 + g;
#pragma unroll
        for (int j = 0; j < 4; j++) {
            int ccol = wn * 32 + j * 8 + t4 * 2;
            atomicAdd(&out[r0 * F_ + ccol],           acc[mi][j][0]);
            atomicAdd(&out[r0 * F_ + ccol + 1],       acc[mi][j][1]);
            atomicAdd(&out[(r0 + 8) * F_ + ccol],     acc[mi][j][2]);
            atomicAdd(&out[(r0 + 8) * F_ + ccol + 1], acc[mi][j][3]);
        }
    }
}

// ---------------------------------------------------------------------------
extern "C" void kernel_launch(void* const* d_in, const int* in_sizes, int n_in,
                              void* d_out, int out_size) {
    const float* x    = (const float*)d_in[0];
    const float* kern = (const float*)d_in[1];
    const float* bias = (const float*)d_in[2];
    const int*   bits = (n_in >= 4) ? (const int*)d_in[3] : nullptr;
    float* out = (float*)d_out;

    static int smemSet = 0;
    if (!smemSet) {
        cudaFuncSetAttribute(gemm_kernel, cudaFuncAttributeMaxDynamicSharedMemorySize, SMEMB);
        smemSet = 1;
    }

    prep_kernel<<<(PREP_TOTAL + 255) / 256, 256>>>(x, kern, (const float4*)bias,
                                                   (float4*)out, bits);
    dim3 gg(NPIX / 64, 9);
    gemm_kernel<<<gg, 256, SMEMB>>>(out);
    relu_kernel<<<(NOUT / 4 + 255) / 256, 256>>>((float4*)out);
}